// round 5
// baseline (speedup 1.0000x reference)
#include <cuda_runtime.h>

// SelfAttention_61804579389661 — GB300 sm_103a — Round 5
//
// Algebraic simplification: softmax over a size-1 axis is identically 1.0,
// so attention == 1 and context[b,u] = sum_s hidden_states[b,s,u].
//
// Status: kernel is at the chip's streaming-read ceiling (~6.3 TB/s measured,
// identical across two decompositions and 2x occupancy — path-independent
// cap). R5 trims the non-streaming remainder: ones-writes folded into the
// streaming blocks (one uniform 512-block wave, no extra grid slice) and a
// deeper unrolled load loop to batch LDGs / cut issue overhead.
//
// Output layout (out_size = 98304 fp32):
//   [0      .. 32767 ]  context   (B=32, U=1024)
//   [32768  .. 98303 ]  attention (B=32, S=2048, 1) == 1.0f

#define BB 32
#define SS 2048
#define UU 1024
#define U4 (UU / 4)        // 256 float4 per row
#define NCHUNK 16          // U-chunks per batch row
#define C4 (U4 / NCHUNK)   // 16 float4 lanes per chunk
#define NT 512             // threads per block
#define SPHASE (NT / C4)   // 32 s-strides per block
#define NITER (SS / SPHASE) // 64 loop iterations

__global__ void __launch_bounds__(NT) fused_kernel(const float4* __restrict__ hs,
                                                   float* __restrict__ out) {
    const int b = blockIdx.x;   // 0..31
    const int y = blockIdx.y;   // 0..15
    const int t = threadIdx.x;  // 0..511

    // ---- ones: attention region = 1.0, spread over all 512 blocks ----
    // 16384 float4 total / 512 blocks = 32 float4 per block (threads 0..31).
    if (t < 32) {
        float4* ones = (float4*)(out + BB * UU);
        ones[(b * NCHUNK + y) * 32 + t] = make_float4(1.f, 1.f, 1.f, 1.f);
    }

    // ---- block (b, y): sum hs[b, :, y*64 : y*64+64] over all S ----
    const int lane = t & (C4 - 1);      // 0..15 -> float4 column in chunk
    const int srow = t >> 4;            // 0..31 -> starting s, stride 32

    const float4* __restrict__ base =
        hs + ((size_t)b * SS + srow) * U4 + y * C4 + lane;

    float4 a0 = make_float4(0.f, 0.f, 0.f, 0.f);
    float4 a1 = make_float4(0.f, 0.f, 0.f, 0.f);
#pragma unroll
    for (int s = 0; s < NITER; s += 16) {
        float4 v[16];
#pragma unroll
        for (int j = 0; j < 16; ++j)                    // front-batched loads
            v[j] = __ldcs(base + (size_t)(s + j) * SPHASE * U4);
#pragma unroll
        for (int j = 0; j < 16; j += 2) {
            a0.x += v[j].x;   a0.y += v[j].y;   a0.z += v[j].z;   a0.w += v[j].w;
            a1.x += v[j+1].x; a1.y += v[j+1].y; a1.z += v[j+1].z; a1.w += v[j+1].w;
        }
    }
    float4 acc = make_float4(a0.x + a1.x, a0.y + a1.y, a0.z + a1.z, a0.w + a1.w);

    // ---- deterministic in-block reduction of the 32 s-phases ----
    __shared__ float4 smem[NT];
    smem[t] = acc;
    __syncthreads();

    if (t < C4) {
        float4 r = make_float4(0.f, 0.f, 0.f, 0.f);
#pragma unroll
        for (int k = 0; k < SPHASE; ++k) {              // fixed order
            float4 v = smem[k * C4 + t];
            r.x += v.x; r.y += v.y; r.z += v.z; r.w += v.w;
        }
        ((float4*)out)[b * U4 + y * C4 + t] = r;
    }
}

extern "C" void kernel_launch(void* const* d_in, const int* in_sizes, int n_in,
                              void* d_out, int out_size) {
    // Inputs: [0]=s_prev, [1]=hidden_states, [2]=Ww, [3]=Wb, [4]=Uw, [5]=Ub,
    //         [6]=Vw, [7]=Vb. Only hidden_states is live.
    const float4* hs = (const float4*)d_in[1];
    float* out = (float*)d_out;

    dim3 grid(BB, NCHUNK);
    fused_kernel<<<grid, NT>>>(hs, out);
}

// round 6
// speedup vs baseline: 1.0346x; 1.0346x over previous
#include <cuda_runtime.h>

// SelfAttention_61804579389661 — GB300 sm_103a — Round 6
//
// Algebraic simplification: softmax over a size-1 axis is identically 1.0,
// so attention == 1 and context[b,u] = sum_s hidden_states[b,s,u].
//
// R6 = R4's proven streaming loop (simple #pragma unroll 8 — ptxas schedules
// it to the 6.3 TB/s chip ceiling; R5's hand-batched unroll regressed it)
// + R5's ones-folding, moved to the epilogue so the launch wavefront is
// pure loads. One uniform 512-block wave, zero cross-block communication.
//
// Output layout (out_size = 98304 fp32):
//   [0      .. 32767 ]  context   (B=32, U=1024)
//   [32768  .. 98303 ]  attention (B=32, S=2048, 1) == 1.0f

#define BB 32
#define SS 2048
#define UU 1024
#define U4 (UU / 4)        // 256 float4 per row
#define NCHUNK 16          // U-chunks per batch row
#define C4 (U4 / NCHUNK)   // 16 float4 lanes per chunk
#define NT 512             // threads per block
#define SPHASE (NT / C4)   // 32 s-strides per block

__global__ void __launch_bounds__(NT) fused_kernel(const float4* __restrict__ hs,
                                                   float* __restrict__ out) {
    const int b = blockIdx.x;   // 0..31
    const int y = blockIdx.y;   // 0..15
    const int t = threadIdx.x;  // 0..511

    // ---- block (b, y): sum hs[b, :, y*64 : y*64+64] over all S ----
    const int lane = t & (C4 - 1);      // 0..15 -> float4 column in chunk
    const int srow = t >> 4;            // 0..31 -> starting s, stride 32

    const float4* __restrict__ base =
        hs + ((size_t)b * SS + srow) * U4 + y * C4 + lane;

    float4 acc = make_float4(0.f, 0.f, 0.f, 0.f);
#pragma unroll 8
    for (int s = 0; s < SS / SPHASE; ++s) {             // 64 iters, stride 32 rows
        float4 v = __ldcs(base + (size_t)s * SPHASE * U4);
        acc.x += v.x; acc.y += v.y; acc.z += v.z; acc.w += v.w;
    }

    // ---- deterministic in-block reduction of the 32 s-phases ----
    __shared__ float4 smem[NT];
    smem[t] = acc;
    __syncthreads();

    if (t < C4) {
        float4 r = make_float4(0.f, 0.f, 0.f, 0.f);
#pragma unroll
        for (int k = 0; k < SPHASE; ++k) {              // fixed order
            float4 v = smem[k * C4 + t];
            r.x += v.x; r.y += v.y; r.z += v.z; r.w += v.w;
        }
        ((float4*)out)[b * U4 + y * C4 + t] = r;
    }

    // ---- epilogue: attention region = 1.0, spread over all 512 blocks ----
    // 16384 float4 total / 512 blocks = 32 float4 per block (threads 32..63,
    // disjoint from the context-writing threads 0..15).
    if (t >= 32 && t < 64) {
        float4* ones = (float4*)(out + BB * UU);
        ones[(b * NCHUNK + y) * 32 + (t - 32)] = make_float4(1.f, 1.f, 1.f, 1.f);
    }
}

extern "C" void kernel_launch(void* const* d_in, const int* in_sizes, int n_in,
                              void* d_out, int out_size) {
    // Inputs: [0]=s_prev, [1]=hidden_states, [2]=Ww, [3]=Wb, [4]=Uw, [5]=Ub,
    //         [6]=Vw, [7]=Vb. Only hidden_states is live.
    const float4* hs = (const float4*)d_in[1];
    float* out = (float*)d_out;

    dim3 grid(BB, NCHUNK);
    fused_kernel<<<grid, NT>>>(hs, out);
}